// round 1
// baseline (speedup 1.0000x reference)
#include <cuda_runtime.h>
#include <math.h>

// VIN forward, B=128, C_in=2, H=W=64, n_hidden=150 (collapsed), n_q=10, num_vi sweeps.
// One CTA per batch image. Everything after the input read lives in SMEM.

#define HH      64
#define PITCH   68          // padded row pitch (floats) for reward / v buffers
#define PR      66          // padded rows
#define NQ      10
#define THREADS 512

// SMEM float layout:
//  qr   : NQ * 4096              = 40960
//  rw   : PR*PITCH               =  4488   (padded reward, zero halo)
//  v0   : PR*PITCH               =  4488   (padded v, zero halo)
//  v1   : PR*PITCH               =  4488
//  wq 90, wv 90, wfc 80, weff 18, beff 1, pad -> 280
#define SMEM_FLOATS (NQ*4096 + 3*PR*PITCH + 280)
#define SMEM_BYTES  (SMEM_FLOATS * 4)

__global__ __launch_bounds__(THREADS, 1)
void vin_kernel(const float* __restrict__ input,    // [128,2,64,64]
                const int*   __restrict__ state_x,  // [128]
                const int*   __restrict__ state_y,  // [128]
                const int*   __restrict__ num_vi_p, // [1]
                const float* __restrict__ W_h,      // [150,2,3,3]
                const float* __restrict__ b_h,      // [150]
                const float* __restrict__ W_r,      // [150]
                const float* __restrict__ W_q,      // [10,9]
                const float* __restrict__ W_v,      // [10,9]
                const float* __restrict__ W_fc,     // [8,10]
                float* __restrict__ out, int out_half)
{
    extern __shared__ float sm[];
    float* qr   = sm;                       // NQ*4096
    float* rw   = qr + NQ*4096;             // PR*PITCH
    float* v0   = rw + PR*PITCH;
    float* v1   = v0 + PR*PITCH;
    float* wq   = v1 + PR*PITCH;            // 90
    float* wv   = wq + 90;                  // 90
    float* wfc  = wv + 90;                  // 80
    float* weff = wfc + 80;                 // 18
    float* beff = weff + 18;                // 1

    const int tid = threadIdx.x;
    const int b   = blockIdx.x;

    // ---- small weights into SMEM (disjoint thread ranges) ----
    if (tid < 90) wq[tid] = W_q[tid];
    {
        int t = tid - 128; if (t >= 0 && t < 90) wv[t] = W_v[t];
    }
    {
        int t = tid - 256; if (t >= 0 && t < 80) wfc[t] = W_fc[t];
    }
    {
        int t = tid - 384;
        if (t >= 0 && t < 19) {
            float s = 0.f;
            if (t < 18) {
                #pragma unroll 1
                for (int h = 0; h < 150; h++) s += W_r[h] * W_h[h*18 + t];
                weff[t] = s;
            } else {
                #pragma unroll 1
                for (int h = 0; h < 150; h++) s += W_r[h] * b_h[h];
                *beff = s;
            }
        }
    }
    // zero rw, v0, v1 (contiguous): halos stay zero forever
    for (int i = tid; i < 3*PR*PITCH; i += THREADS) rw[i] = 0.f;
    __syncthreads();

    // ---- thread -> pixel mapping: 8 consecutive x per thread ----
    const int y  = tid >> 3;          // 0..63
    const int x0 = (tid & 7) << 3;    // 0,8,...,56

    // ---- Phase B: reward = conv(input, W_eff, pad=1) + b_eff ----
    {
        const float* inb = input + (size_t)b * 2 * 4096;
        float acc[8];
        const float be = *beff;
        #pragma unroll
        for (int i = 0; i < 8; i++) acc[i] = be;
        #pragma unroll
        for (int c = 0; c < 2; c++) {
            const float* ic = inb + c * 4096;
            #pragma unroll
            for (int dy = 0; dy < 3; dy++) {
                int gy = y + dy - 1;
                float r[10];
                #pragma unroll
                for (int j = 0; j < 10; j++) {
                    int gx = x0 + j - 1;
                    r[j] = (gy >= 0 && gy < 64 && gx >= 0 && gx < 64)
                           ? ic[gy*64 + gx] : 0.f;
                }
                #pragma unroll
                for (int kx = 0; kx < 3; kx++) {
                    float w = weff[c*9 + dy*3 + kx];
                    #pragma unroll
                    for (int i = 0; i < 8; i++) acc[i] = fmaf(w, r[i+kx], acc[i]);
                }
            }
        }
        #pragma unroll
        for (int i = 0; i < 8; i++) rw[(y+1)*PITCH + (x0+1) + i] = acc[i];
    }
    __syncthreads();

    // ---- Phase C: qr[ch] = conv(reward, W_q[ch], pad=1); v0 = max_ch qr ----
    {
        float r[3][10];
        #pragma unroll
        for (int dy = 0; dy < 3; dy++) {
            const float* rp = rw + (y+dy)*PITCH + x0;   // 16B aligned
            float4 a0 = *(const float4*)(rp);
            float4 a1 = *(const float4*)(rp + 4);
            float2 a2 = *(const float2*)(rp + 8);
            r[dy][0]=a0.x; r[dy][1]=a0.y; r[dy][2]=a0.z; r[dy][3]=a0.w;
            r[dy][4]=a1.x; r[dy][5]=a1.y; r[dy][6]=a1.z; r[dy][7]=a1.w;
            r[dy][8]=a2.x; r[dy][9]=a2.y;
        }
        float vmax[8];
        #pragma unroll
        for (int i = 0; i < 8; i++) vmax[i] = -1e30f;
        #pragma unroll
        for (int ch = 0; ch < NQ; ch++) {
            float a[8];
            #pragma unroll
            for (int i = 0; i < 8; i++) a[i] = 0.f;
            #pragma unroll
            for (int dy = 0; dy < 3; dy++) {
                #pragma unroll
                for (int kx = 0; kx < 3; kx++) {
                    float w = wq[ch*9 + dy*3 + kx];
                    #pragma unroll
                    for (int i = 0; i < 8; i++) a[i] = fmaf(w, r[dy][i+kx], a[i]);
                }
            }
            float* qp = qr + ch*4096 + y*64 + x0;       // 16B aligned
            *(float4*)(qp)     = make_float4(a[0], a[1], a[2], a[3]);
            *(float4*)(qp + 4) = make_float4(a[4], a[5], a[6], a[7]);
            #pragma unroll
            for (int i = 0; i < 8; i++) vmax[i] = fmaxf(vmax[i], a[i]);
        }
        #pragma unroll
        for (int i = 0; i < 8; i++) v0[(y+1)*PITCH + (x0+1) + i] = vmax[i];
    }
    __syncthreads();

    // ---- Phase D: value-iteration sweeps, all in SMEM ----
    const int iters = num_vi_p[0] - 1;
    float* vc = v0;
    float* vn = v1;
    for (int it = 0; it < iters; it++) {
        float r[3][10];
        #pragma unroll
        for (int dy = 0; dy < 3; dy++) {
            const float* rp = vc + (y+dy)*PITCH + x0;
            float4 a0 = *(const float4*)(rp);
            float4 a1 = *(const float4*)(rp + 4);
            float2 a2 = *(const float2*)(rp + 8);
            r[dy][0]=a0.x; r[dy][1]=a0.y; r[dy][2]=a0.z; r[dy][3]=a0.w;
            r[dy][4]=a1.x; r[dy][5]=a1.y; r[dy][6]=a1.z; r[dy][7]=a1.w;
            r[dy][8]=a2.x; r[dy][9]=a2.y;
        }
        float vmax[8];
        #pragma unroll
        for (int i = 0; i < 8; i++) vmax[i] = -1e30f;
        #pragma unroll
        for (int ch = 0; ch < NQ; ch++) {
            const float* qp = qr + ch*4096 + y*64 + x0;
            float4 q0 = *(const float4*)(qp);
            float4 q1 = *(const float4*)(qp + 4);
            float a[8] = {q0.x, q0.y, q0.z, q0.w, q1.x, q1.y, q1.z, q1.w};
            #pragma unroll
            for (int dy = 0; dy < 3; dy++) {
                #pragma unroll
                for (int kx = 0; kx < 3; kx++) {
                    float w = wv[ch*9 + dy*3 + kx];
                    #pragma unroll
                    for (int i = 0; i < 8; i++) a[i] = fmaf(w, r[dy][i+kx], a[i]);
                }
            }
            #pragma unroll
            for (int i = 0; i < 8; i++) vmax[i] = fmaxf(vmax[i], a[i]);
        }
        #pragma unroll
        for (int i = 0; i < 8; i++) vn[(y+1)*PITCH + (x0+1) + i] = vmax[i];
        __syncthreads();
        float* t = vc; vc = vn; vn = t;
    }

    // ---- Phase E: q at (state_x, state_y), logits, softmax ----
    if (tid == 0) {
        int sx = state_x[b];
        int sy = state_y[b];
        float qxy[NQ];
        #pragma unroll
        for (int ch = 0; ch < NQ; ch++) {
            float s = qr[ch*4096 + sx*64 + sy];
            #pragma unroll
            for (int dy = 0; dy < 3; dy++)
                #pragma unroll
                for (int kx = 0; kx < 3; kx++)
                    s = fmaf(wv[ch*9 + dy*3 + kx], vc[(sx+dy)*PITCH + (sy+kx)], s);
            qxy[ch] = s;
        }
        float l[8];
        float m = -1e30f;
        #pragma unroll
        for (int j = 0; j < 8; j++) {
            float s = 0.f;
            #pragma unroll
            for (int ch = 0; ch < NQ; ch++) s = fmaf(wfc[j*NQ + ch], qxy[ch], s);
            l[j] = s;
            m = fmaxf(m, s);
        }
        float e[8], den = 0.f;
        #pragma unroll
        for (int j = 0; j < 8; j++) { e[j] = expf(l[j] - m); den += e[j]; }
        float inv = 1.f / den;
        #pragma unroll
        for (int j = 0; j < 8; j++) {
            out[b*8 + j]            = l[j];
            out[out_half + b*8 + j] = e[j] * inv;
        }
    }
}

extern "C" void kernel_launch(void* const* d_in, const int* in_sizes, int n_in,
                              void* d_out, int out_size) {
    const float* input   = (const float*)d_in[0];
    const int*   state_x = (const int*)  d_in[1];
    const int*   state_y = (const int*)  d_in[2];
    const int*   num_vi  = (const int*)  d_in[3];
    const float* W_h     = (const float*)d_in[4];
    const float* b_h     = (const float*)d_in[5];
    const float* W_r     = (const float*)d_in[6];
    const float* W_q     = (const float*)d_in[7];
    const float* W_v     = (const float*)d_in[8];
    const float* W_fc    = (const float*)d_in[9];
    float* out = (float*)d_out;

    static bool attr_set = false;
    if (!attr_set) {
        cudaFuncSetAttribute(vin_kernel,
                             cudaFuncAttributeMaxDynamicSharedMemorySize,
                             SMEM_BYTES);
        attr_set = true;
    }

    vin_kernel<<<128, THREADS, SMEM_BYTES>>>(
        input, state_x, state_y, num_vi, W_h, b_h, W_r, W_q, W_v, W_fc,
        out, out_size / 2);
}